// round 5
// baseline (speedup 1.0000x reference)
#include <cuda_runtime.h>
#include <cuda_bf16.h>
#include <cuda_fp8.h>
#include <cstdint>
#include <math.h>

#define NN 8192
#define HD 1024
#define EE 8192

// ---------------- scratch (device globals; allocation-free) ----------------
__device__ unsigned char g_A8[(size_t)NN * NN];    // 64 MB  fp8 A
__device__ unsigned char g_W18[(size_t)HD * NN];   // 8 MB   fp8 W1
__device__ unsigned char g_W28[(size_t)NN * HD];   // 8 MB   fp8 W2
__device__ unsigned char g_H18[(size_t)NN * HD];   // 8 MB   fp8 H1 (GEMM2 input)
__device__ __nv_bfloat16 g_H1bf[(size_t)NN * HD];  // 16 MB  bf16 H1 (reductions)
__device__ __nv_bfloat16 g_H2bf[(size_t)NN * NN];  // 128 MB bf16 H2 (reductions)
__device__ float g_d2[NN];
__device__ float g_acc[3];

// ---------------- PTX helpers ----------------
__device__ __forceinline__ uint32_t smem_u32(const void* p) {
    uint32_t a;
    asm("{ .reg .u64 t; cvta.to.shared.u64 t, %1; cvt.u32.u64 %0, t; }" : "=r"(a) : "l"(p));
    return a;
}

#define CP_ASYNC16(dst, src) \
    asm volatile("cp.async.cg.shared.global [%0], [%1], 16;" :: "r"(dst), "l"(src) : "memory")
#define CP_COMMIT() asm volatile("cp.async.commit_group;" ::: "memory")
template <int N>
__device__ __forceinline__ void cp_wait() {
    asm volatile("cp.async.wait_group %0;" :: "n"(N) : "memory");
}

__device__ __forceinline__ void ldsm4(uint32_t* r, uint32_t addr) {
    asm volatile("ldmatrix.sync.aligned.m8n8.x4.shared.b16 {%0,%1,%2,%3}, [%4];"
                 : "=r"(r[0]), "=r"(r[1]), "=r"(r[2]), "=r"(r[3]) : "r"(addr));
}

// fp8 e4m3 MMA: D(16x8,f32) += A(16x32) * B(32x8)
__device__ __forceinline__ void mma_fp8(float* c, const uint32_t* a,
                                        uint32_t b0, uint32_t b1) {
    asm volatile(
        "mma.sync.aligned.m16n8k32.row.col.f32.e4m3.e4m3.f32 "
        "{%0,%1,%2,%3}, {%4,%5,%6,%7}, {%8,%9}, {%0,%1,%2,%3};"
        : "+f"(c[0]), "+f"(c[1]), "+f"(c[2]), "+f"(c[3])
        : "r"(a[0]), "r"(a[1]), "r"(a[2]), "r"(a[3]), "r"(b0), "r"(b1));
}

// ---------------- fp8 QMMA GEMM: H = sigmoid(A @ B^T + bias) ----------------
// A: [M, K] fp8 row-major; B: [Nc, K] fp8 row-major (NT); H: [M, Nc] bf16 (+ opt fp8).
// CTA tile 128x128, BK=128 fp8 (128B rows, SW128), 3-stage cp.async ring,
// 4 warps (2x2), warp tile 64x64. Byte-level addressing identical to the
// validated bf16 m16n8k16 scheme (32B k-step, (q>>1)*16B lane offset).
#define STAGE_BYTES 32768              // A 16K + B 16K
#define SMEM_BYTES (3 * STAGE_BYTES + 512)

__device__ __forceinline__ void load_stage(
    const unsigned char* __restrict__ A8, const unsigned char* __restrict__ B8,
    int K, int bm0, int bn0, int kt, uint32_t stageBase, int tid)
{
#pragma unroll
    for (int r = 0; r < 8; r++) {
        int idx = tid + r * 128;           // 0..1023
        int row = idx >> 3, ck = idx & 7;  // 128 rows x 8 chunks of 16B
        uint32_t off = (uint32_t)(row * 128 + ck * 16);
        uint32_t sw = off ^ ((off >> 3) & 0x70);
        const void* srcA = A8 + (size_t)(bm0 + row) * K + kt + ck * 16;
        CP_ASYNC16(stageBase + sw, srcA);
        const void* srcB = B8 + (size_t)(bn0 + row) * K + kt + ck * 16;
        CP_ASYNC16(stageBase + 16384 + sw, srcB);
    }
    CP_COMMIT();
}

__global__ void __launch_bounds__(128, 2)
gemm_qmma_bias_sigmoid(const unsigned char* __restrict__ A8,
                       const unsigned char* __restrict__ B8,
                       const float* __restrict__ bias,
                       __nv_bfloat16* __restrict__ Hout,
                       unsigned char* __restrict__ Hout8,   // optional fp8 copy
                       int K, int Nc)
{
    extern __shared__ __align__(1024) char smem[];
    const uint32_t sb0 = smem_u32(smem);
    float* biasS = (float*)(smem + 3 * STAGE_BYTES);
    const int tid = threadIdx.x;
    const int wid = tid >> 5, lid = tid & 31;
    const int warp_m = wid >> 1;     // 0..1 -> 64 rows
    const int warp_n = wid & 1;      // 0..1 -> 64 cols
    const int bm0 = blockIdx.y * 128;
    const int bn0 = blockIdx.x * 128;

    // per-lane ldmatrix addressing (byte-identical to validated bf16 scheme)
    const int q  = lid >> 3;         // matrix index 0..3
    const int r8 = lid & 7;
    const int arowb = warp_m * 64 + (q & 1) * 8 + r8;   // + mt*16
    const int browb = warp_n * 64 + (q & 1) * 8 + r8;   // + bt*16
    const uint32_t kq   = (uint32_t)((q >> 1) * 16);    // bytes
    const uint32_t axor = (uint32_t)((arowb & 7) << 4);
    const uint32_t bxor = (uint32_t)((browb & 7) << 4);

    biasS[tid] = bias[bn0 + tid];

    float acc[4][8][4];
#pragma unroll
    for (int i = 0; i < 4; i++)
#pragma unroll
        for (int j = 0; j < 8; j++)
#pragma unroll
            for (int k = 0; k < 4; k++) acc[i][j][k] = 0.f;

    const int T = K >> 7;            // K/128 fp8 chunks

    load_stage(A8, B8, K, bm0, bn0, 0, sb0, tid);
    load_stage(A8, B8, K, bm0, bn0, 128, sb0 + STAGE_BYTES, tid);

    uint32_t af[2][4][4];            // [buf][mt][4]
    uint32_t bf2[2][4][4];           // [buf][bt][4]

    for (int i = 0; i < T; i++) {
        if (i < T - 1) cp_wait<1>(); else cp_wait<0>();
        __syncthreads();
        if (i + 2 < T) {
            int pb = (i + 2) % 3;
            load_stage(A8, B8, K, bm0, bn0, (i + 2) * 128,
                       sb0 + (uint32_t)pb * STAGE_BYTES, tid);
        }
        const uint32_t Ab = sb0 + (uint32_t)(i % 3) * STAGE_BYTES;
        const uint32_t Bb = Ab + 16384;

        // fragment prefetch for s=0 (k-bytes 0..31 of this 128B chunk)
        {
            const uint32_t koff = kq;
#pragma unroll
            for (int mt = 0; mt < 4; mt++)
                ldsm4(af[0][mt], Ab + (uint32_t)(arowb + mt * 16) * 128 + (koff ^ axor));
#pragma unroll
            for (int bt = 0; bt < 4; bt++)
                ldsm4(bf2[0][bt], Bb + (uint32_t)(browb + bt * 16) * 128 + (koff ^ bxor));
        }
#pragma unroll
        for (int s = 0; s < 4; s++) {    // 4 k32 steps x 32B
            const int cur = s & 1;
            if (s < 3) {
                const int nxt = cur ^ 1;
                const uint32_t koff = (uint32_t)((s + 1) * 32) | kq;
#pragma unroll
                for (int mt = 0; mt < 4; mt++)
                    ldsm4(af[nxt][mt], Ab + (uint32_t)(arowb + mt * 16) * 128 + (koff ^ axor));
#pragma unroll
                for (int bt = 0; bt < 4; bt++)
                    ldsm4(bf2[nxt][bt], Bb + (uint32_t)(browb + bt * 16) * 128 + (koff ^ bxor));
            }
#pragma unroll
            for (int mt = 0; mt < 4; mt++)
#pragma unroll
                for (int nt = 0; nt < 8; nt++)
                    mma_fp8(acc[mt][nt], af[cur][mt],
                            bf2[cur][nt >> 1][nt & 1], bf2[cur][nt >> 1][(nt & 1) + 2]);
        }
    }

    // epilogue: bias + sigmoid + bf16 store (+ optional fp8 store)
    const int rr = lid >> 2;              // 0..7
    const int cc = (lid & 3) * 2;
#pragma unroll
    for (int nt = 0; nt < 8; nt++) {
        const int coll = warp_n * 64 + nt * 8 + cc;
        const int col = bn0 + coll;
        const float bb0 = biasS[coll], bb1 = biasS[coll + 1];
#pragma unroll
        for (int mt = 0; mt < 4; mt++) {
            const int row0 = bm0 + warp_m * 64 + mt * 16 + rr;
            float v0 = acc[mt][nt][0] + bb0, v1 = acc[mt][nt][1] + bb1;
            float v2 = acc[mt][nt][2] + bb0, v3 = acc[mt][nt][3] + bb1;
            float s0 = 1.f / (1.f + __expf(-v0));
            float s1 = 1.f / (1.f + __expf(-v1));
            float s2 = 1.f / (1.f + __expf(-v2));
            float s3 = 1.f / (1.f + __expf(-v3));
            __nv_bfloat162 h01 = __floats2bfloat162_rn(s0, s1);
            __nv_bfloat162 h23 = __floats2bfloat162_rn(s2, s3);
            *(uint32_t*)(Hout + (size_t)row0 * Nc + col)       = *(uint32_t*)&h01;
            *(uint32_t*)(Hout + (size_t)(row0 + 8) * Nc + col) = *(uint32_t*)&h23;
            if (Hout8) {
                __nv_fp8x2_storage_t f01 = __nv_cvt_float2_to_fp8x2(
                    make_float2(s0, s1), __NV_SATFINITE, __NV_E4M3);
                __nv_fp8x2_storage_t f23 = __nv_cvt_float2_to_fp8x2(
                    make_float2(s2, s3), __NV_SATFINITE, __NV_E4M3);
                *(uint16_t*)(Hout8 + (size_t)row0 * Nc + col)       = (uint16_t)f01;
                *(uint16_t*)(Hout8 + (size_t)(row0 + 8) * Nc + col) = (uint16_t)f23;
            }
        }
    }
}

// ---------------- fp32 -> fp8 conversion (16 elems/thread, MLP=4) ----------------
__global__ void f32_to_f8(const float4* __restrict__ in, uint4* __restrict__ out, int n16) {
    int i = blockIdx.x * blockDim.x + threadIdx.x;
    if (i < n16) {
        float4 v[4];
#pragma unroll
        for (int j = 0; j < 4; j++) v[j] = in[i * 4 + j];
        uint32_t r[4];
#pragma unroll
        for (int j = 0; j < 4; j++) {
            __nv_fp8x2_storage_t lo = __nv_cvt_float2_to_fp8x2(
                make_float2(v[j].x, v[j].y), __NV_SATFINITE, __NV_E4M3);
            __nv_fp8x2_storage_t hi = __nv_cvt_float2_to_fp8x2(
                make_float2(v[j].z, v[j].w), __NV_SATFINITE, __NV_E4M3);
            r[j] = (uint32_t)lo | ((uint32_t)hi << 16);
        }
        out[i] = make_uint4(r[0], r[1], r[2], r[3]);
    }
}

// ---------------- reductions ----------------
__device__ __forceinline__ float block_reduce(float v) {
    __shared__ float sh[8];
    __syncthreads();
    int lane = threadIdx.x & 31;
    int w    = threadIdx.x >> 5;
#pragma unroll
    for (int o = 16; o > 0; o >>= 1) v += __shfl_down_sync(0xffffffffu, v, o);
    if (lane == 0) sh[w] = v;
    __syncthreads();
    if (w == 0) {
        v = (lane < 8) ? sh[lane] : 0.f;
#pragma unroll
        for (int o = 4; o > 0; o >>= 1) v += __shfl_down_sync(0xffffffffu, v, o);
    }
    return v;
}

__device__ __forceinline__ float d2_bf8(uint4 x, uint4 y) {
    float s = 0.f;
    const uint32_t* xp = (const uint32_t*)&x;
    const uint32_t* yp = (const uint32_t*)&y;
#pragma unroll
    for (int qq = 0; qq < 4; qq++) {
        float2 a = __bfloat1622float2(*(const __nv_bfloat162*)&xp[qq]);
        float2 b = __bfloat1622float2(*(const __nv_bfloat162*)&yp[qq]);
        float d0 = a.x - b.x, d1 = a.y - b.y;
        s += d0 * d0 + d1 * d1;
    }
    return s;
}

__global__ void zero_acc_kernel() { g_acc[0] = 0.f; g_acc[1] = 0.f; g_acc[2] = 0.f; }

// d2[n] = || A[n,:] - H2[n,:] ||  (A fp32, H2 bf16)
__global__ void node_residual_kernel(const float* __restrict__ A) {
    int n = blockIdx.x;
    const float4* a = (const float4*)(A + (size_t)n * NN);
    const uint2* h  = (const uint2*)(g_H2bf + (size_t)n * NN);
    float s = 0.f;
    for (int c = threadIdx.x; c < NN / 4; c += blockDim.x) {
        float4 x = a[c];
        uint2 hh = h[c];
        float2 h0 = __bfloat1622float2(*(const __nv_bfloat162*)&hh.x);
        float2 h1 = __bfloat1622float2(*(const __nv_bfloat162*)&hh.y);
        float d0 = x.x - h0.x, d1 = x.y - h0.y, d2v = x.z - h1.x, d3 = x.w - h1.y;
        s += d0 * d0 + d1 * d1 + d2v * d2v + d3 * d3;
    }
    s = block_reduce(s);
    if (threadIdx.x == 0) g_d2[n] = sqrtf(s);
}

__global__ void edge_loss_kernel(const int* __restrict__ edges,
                                 const int* __restrict__ labels) {
    int e  = blockIdx.x;
    int ni = edges[2 * e + 0];
    int nj = edges[2 * e + 1];
    int lab = labels[e];

    if (lab != 0) {
        const uint4* hi1 = (const uint4*)(g_H1bf + (size_t)ni * HD);
        const uint4* hj1 = (const uint4*)(g_H1bf + (size_t)nj * HD);
        float s1 = 0.f;
        for (int c = threadIdx.x; c < HD / 8; c += blockDim.x)
            s1 += d2_bf8(hi1[c], hj1[c]);
        const uint4* hi2 = (const uint4*)(g_H2bf + (size_t)ni * NN);
        const uint4* hj2 = (const uint4*)(g_H2bf + (size_t)nj * NN);
        float s2 = 0.f;
        for (int c = threadIdx.x; c < NN / 8; c += blockDim.x)
            s2 += d2_bf8(hi2[c], hj2[c]);
        s1 = block_reduce(s1);
        s2 = block_reduce(s2);
        if (threadIdx.x == 0) atomicAdd(&g_acc[0], sqrtf(s1) + sqrtf(s2));
    }
    if (threadIdx.x == 0) {
        float factor = (lab != 0) ? 10.f : 1.f;
        atomicAdd(&g_acc[1], factor * (g_d2[ni] + g_d2[nj]));
    }
}

// sum of row norms of W1, W2 plus ||b1||, ||b2|| (exact, fp32 inputs)
__global__ void reg_norm_kernel(const float* __restrict__ W1, const float* __restrict__ b1,
                                const float* __restrict__ W2, const float* __restrict__ b2) {
    int b = blockIdx.x;
    const float* p; int len;
    if (b < HD)            { p = W1 + (size_t)b * NN;        len = NN; }
    else if (b < HD + NN)  { p = W2 + (size_t)(b - HD) * HD; len = HD; }
    else if (b == HD + NN) { p = b1;                         len = HD; }
    else                   { p = b2;                         len = NN; }
    float s = 0.f;
    for (int c = threadIdx.x; c < len; c += blockDim.x) { float v = p[c]; s += v * v; }
    s = block_reduce(s);
    if (threadIdx.x == 0) atomicAdd(&g_acc[2], sqrtf(s));
}

__global__ void finalize_kernel(float* out) {
    out[0] = g_acc[0] + g_acc[1] + g_acc[2] * (float)EE;
}

// ---------------- launch ----------------
extern "C" void kernel_launch(void* const* d_in, const int* in_sizes, int n_in,
                              void* d_out, int out_size) {
    const float* A      = (const float*)d_in[0];
    const float* W1     = (const float*)d_in[1];
    const float* b1     = (const float*)d_in[2];
    const float* W2     = (const float*)d_in[3];
    const float* b2     = (const float*)d_in[4];
    const int*   edges  = (const int*)d_in[5];
    const int*   labels = (const int*)d_in[6];
    float* out = (float*)d_out;

    unsigned char *A8, *W18, *W28, *H18;
    __nv_bfloat16 *H1bf, *H2bf;
    cudaGetSymbolAddress((void**)&A8,   g_A8);
    cudaGetSymbolAddress((void**)&W18,  g_W18);
    cudaGetSymbolAddress((void**)&W28,  g_W28);
    cudaGetSymbolAddress((void**)&H18,  g_H18);
    cudaGetSymbolAddress((void**)&H1bf, g_H1bf);
    cudaGetSymbolAddress((void**)&H2bf, g_H2bf);

    cudaFuncSetAttribute(gemm_qmma_bias_sigmoid,
                         cudaFuncAttributeMaxDynamicSharedMemorySize, SMEM_BYTES);

    zero_acc_kernel<<<1, 1>>>();

    // fp32 -> fp8 conversions (16 elems/thread)
    f32_to_f8<<<(NN * (NN / 16) + 255) / 256, 256>>>((const float4*)A,  (uint4*)A8,  NN * NN / 16);
    f32_to_f8<<<(HD * (NN / 16) + 255) / 256, 256>>>((const float4*)W1, (uint4*)W18, HD * NN / 16);
    f32_to_f8<<<(NN * (HD / 16) + 255) / 256, 256>>>((const float4*)W2, (uint4*)W28, NN * HD / 16);

    // H1 = sigmoid(A @ W1^T + b1): M=8192, Nc=1024, K=8192  (writes bf16 + fp8)
    gemm_qmma_bias_sigmoid<<<dim3(HD / 128, NN / 128), 128, SMEM_BYTES>>>(
        A8, W18, b1, H1bf, H18, NN, HD);
    // H2 = sigmoid(H1 @ W2^T + b2): M=8192, Nc=8192, K=1024  (bf16 only)
    gemm_qmma_bias_sigmoid<<<dim3(NN / 128, NN / 128), 128, SMEM_BYTES>>>(
        H18, W28, b2, H2bf, nullptr, HD, NN);

    node_residual_kernel<<<NN, 256>>>(A);
    edge_loss_kernel<<<EE, 256>>>(edges, labels);
    reg_norm_kernel<<<HD + NN + 2, 256>>>(W1, b1, W2, b2);
    finalize_kernel<<<1, 1>>>(out);
}

// round 6
// speedup vs baseline: 1.1272x; 1.1272x over previous
#include <cuda_runtime.h>
#include <cuda_bf16.h>
#include <cstdint>
#include <math.h>

#define NN 8192
#define HD 1024
#define EE 8192

// ---------------- scratch (device globals; allocation-free) ----------------
__device__ __nv_bfloat16 g_Abf[(size_t)NN * NN];   // 128 MB
__device__ __nv_bfloat16 g_W1bf[(size_t)HD * NN];  // 16 MB
__device__ __nv_bfloat16 g_W2bf[(size_t)NN * HD];  // 16 MB
__device__ __nv_bfloat16 g_H1bf[(size_t)NN * HD];  // 16 MB
__device__ __nv_bfloat16 g_H2bf[(size_t)NN * NN];  // 128 MB
__device__ float g_d2sq[NN];
__device__ float g_acc[3];

// ---------------- PTX helpers ----------------
__device__ __forceinline__ uint32_t smem_u32(const void* p) {
    uint32_t a;
    asm("{ .reg .u64 t; cvta.to.shared.u64 t, %1; cvt.u32.u64 %0, t; }" : "=r"(a) : "l"(p));
    return a;
}

#define CP_ASYNC16(dst, src) \
    asm volatile("cp.async.cg.shared.global [%0], [%1], 16;" :: "r"(dst), "l"(src) : "memory")
#define CP_COMMIT() asm volatile("cp.async.commit_group;" ::: "memory")
template <int N>
__device__ __forceinline__ void cp_wait() {
    asm volatile("cp.async.wait_group %0;" :: "n"(N) : "memory");
}

__device__ __forceinline__ void ldsm4(uint32_t* r, uint32_t addr) {
    asm volatile("ldmatrix.sync.aligned.m8n8.x4.shared.b16 {%0,%1,%2,%3}, [%4];"
                 : "=r"(r[0]), "=r"(r[1]), "=r"(r[2]), "=r"(r[3]) : "r"(addr));
}

__device__ __forceinline__ void mma_bf16(float* c, const uint32_t* a,
                                         uint32_t b0, uint32_t b1) {
    asm volatile(
        "mma.sync.aligned.m16n8k16.row.col.f32.bf16.bf16.f32 "
        "{%0,%1,%2,%3}, {%4,%5,%6,%7}, {%8,%9}, {%0,%1,%2,%3};"
        : "+f"(c[0]), "+f"(c[1]), "+f"(c[2]), "+f"(c[3])
        : "r"(a[0]), "r"(a[1]), "r"(a[2]), "r"(a[3]), "r"(b0), "r"(b1));
}

// ---------------- bf16 HMMA GEMM: H = sigmoid(A @ B^T + bias) ----------------
// A: [M, K] bf16 row-major; B: [Nc, K] bf16 row-major (NT); H: [M, Nc] bf16.
// CTA tile 128x128, BK=64, 3-stage cp.async pipeline, 8 warps (2x4), warp 64x32.
// Optional fused residual: if Afp32 != nullptr, accumulates per-row
// sum((Afp32[r,c] - sigmoid)^2) into d2sq via atomics (fp32 pre-rounding values).
#define STAGE_BYTES 32768          // A 16K + B 16K
#define SMEM_BYTES (3 * STAGE_BYTES)

__device__ __forceinline__ void load_stage(
    const __nv_bfloat16* __restrict__ Abf, const __nv_bfloat16* __restrict__ Bbf,
    int K, int bm0, int bn0, int kt, uint32_t stageBase, int tid)
{
#pragma unroll
    for (int r = 0; r < 4; r++) {
        int idx = tid + r * 256;           // 0..1023
        int row = idx >> 3, ck = idx & 7;  // 128 rows x 8 chunks of 16B
        uint32_t off = (uint32_t)(row * 128 + ck * 16);
        uint32_t sw = off ^ ((off >> 3) & 0x70);
        const void* srcA = (const char*)(Abf + (size_t)(bm0 + row) * K + kt) + ck * 16;
        CP_ASYNC16(stageBase + sw, srcA);
        const void* srcB = (const char*)(Bbf + (size_t)(bn0 + row) * K + kt) + ck * 16;
        CP_ASYNC16(stageBase + 16384 + sw, srcB);
    }
    CP_COMMIT();
}

__global__ void __launch_bounds__(256)
gemm_hmma_bias_sigmoid(const __nv_bfloat16* __restrict__ Abf,
                       const __nv_bfloat16* __restrict__ Bbf,
                       const float* __restrict__ bias,
                       __nv_bfloat16* __restrict__ Hout,
                       const float* __restrict__ Afp32,   // optional fused residual
                       float* __restrict__ d2sq,
                       int K, int Nc)
{
    extern __shared__ __align__(1024) char smem[];
    const uint32_t sb0 = smem_u32(smem);
    const int tid = threadIdx.x;
    const int wid = tid >> 5, lid = tid & 31;
    const int warp_m = wid >> 2;     // 0..1 -> 64 rows
    const int warp_n = wid & 3;      // 0..3 -> 32 cols
    const int bm0 = blockIdx.y * 128;
    const int bn0 = blockIdx.x * 128;

    // per-lane ldmatrix addressing constants
    const int q  = lid >> 3;         // matrix index 0..3
    const int r8 = lid & 7;
    const int arowb = warp_m * 64 + (q & 1) * 8 + r8;   // + mt*16
    const int browb = warp_n * 32 + (q & 1) * 8 + r8;   // + bt*16
    const uint32_t kq   = (uint32_t)((q >> 1) * 16);
    const uint32_t axor = (uint32_t)((arowb & 7) << 4);
    const uint32_t bxor = (uint32_t)((browb & 7) << 4);

    float acc[4][4][4];
#pragma unroll
    for (int i = 0; i < 4; i++)
#pragma unroll
        for (int j = 0; j < 4; j++)
#pragma unroll
            for (int k = 0; k < 4; k++) acc[i][j][k] = 0.f;

    const int T = K >> 6;            // K/64 chunks

    load_stage(Abf, Bbf, K, bm0, bn0, 0, sb0, tid);
    load_stage(Abf, Bbf, K, bm0, bn0, 64, sb0 + STAGE_BYTES, tid);

    for (int i = 0; i < T; i++) {
        if (i < T - 1) cp_wait<1>(); else cp_wait<0>();
        __syncthreads();
        if (i + 2 < T) {
            int pb = (i + 2) % 3;
            load_stage(Abf, Bbf, K, bm0, bn0, (i + 2) * 64,
                       sb0 + (uint32_t)pb * STAGE_BYTES, tid);
        }
        const uint32_t Ab = sb0 + (uint32_t)(i % 3) * STAGE_BYTES;
        const uint32_t Bb = Ab + 16384;

#pragma unroll
        for (int s = 0; s < 4; s++) {
            const uint32_t koff = (uint32_t)(s * 32) | kq;
            uint32_t a[4][4], bfr[2][4];
#pragma unroll
            for (int mt = 0; mt < 4; mt++)
                ldsm4(a[mt], Ab + (uint32_t)(arowb + mt * 16) * 128 + (koff ^ axor));
#pragma unroll
            for (int bt = 0; bt < 2; bt++)
                ldsm4(bfr[bt], Bb + (uint32_t)(browb + bt * 16) * 128 + (koff ^ bxor));
#pragma unroll
            for (int mt = 0; mt < 4; mt++)
#pragma unroll
                for (int nt = 0; nt < 4; nt++)
                    mma_bf16(acc[mt][nt], a[mt], bfr[nt >> 1][nt & 1], bfr[nt >> 1][(nt & 1) + 2]);
        }
        __syncthreads();
    }

    // epilogue: bias + sigmoid + bf16 store (+ optional fused residual)
    const int rr = lid >> 2;              // 0..7
    const int cc = (lid & 3) * 2;
    float sum0[4] = {0.f, 0.f, 0.f, 0.f}; // per-mt row0 partials
    float sum8[4] = {0.f, 0.f, 0.f, 0.f}; // per-mt row0+8 partials

#pragma unroll
    for (int nt = 0; nt < 4; nt++) {
        const int col = bn0 + warp_n * 32 + nt * 8 + cc;
        const float bb0 = bias[col], bb1 = bias[col + 1];
#pragma unroll
        for (int mt = 0; mt < 4; mt++) {
            const int row0 = bm0 + warp_m * 64 + mt * 16 + rr;
            float v0 = acc[mt][nt][0] + bb0, v1 = acc[mt][nt][1] + bb1;
            float v2 = acc[mt][nt][2] + bb0, v3 = acc[mt][nt][3] + bb1;
            float s0 = 1.f / (1.f + __expf(-v0));
            float s1 = 1.f / (1.f + __expf(-v1));
            float s2 = 1.f / (1.f + __expf(-v2));
            float s3 = 1.f / (1.f + __expf(-v3));
            __nv_bfloat162 h01 = __floats2bfloat162_rn(s0, s1);
            __nv_bfloat162 h23 = __floats2bfloat162_rn(s2, s3);
            if (Afp32) {
                // streaming store (H2 read once, much later)
                __stcs((unsigned int*)(Hout + (size_t)row0 * Nc + col), *(unsigned int*)&h01);
                __stcs((unsigned int*)(Hout + (size_t)(row0 + 8) * Nc + col), *(unsigned int*)&h23);
                float2 a01 = __ldcs((const float2*)(Afp32 + (size_t)row0 * Nc + col));
                float2 a23 = __ldcs((const float2*)(Afp32 + (size_t)(row0 + 8) * Nc + col));
                float d0 = a01.x - s0, d1 = a01.y - s1;
                float d2v = a23.x - s2, d3 = a23.y - s3;
                sum0[mt] += d0 * d0 + d1 * d1;
                sum8[mt] += d2v * d2v + d3 * d3;
            } else {
                *(uint32_t*)(Hout + (size_t)row0 * Nc + col)       = *(uint32_t*)&h01;
                *(uint32_t*)(Hout + (size_t)(row0 + 8) * Nc + col) = *(uint32_t*)&h23;
            }
        }
    }

    if (Afp32) {
#pragma unroll
        for (int mt = 0; mt < 4; mt++) {
            float s0v = sum0[mt], s8v = sum8[mt];
            s0v += __shfl_xor_sync(0xffffffffu, s0v, 1);
            s0v += __shfl_xor_sync(0xffffffffu, s0v, 2);
            s8v += __shfl_xor_sync(0xffffffffu, s8v, 1);
            s8v += __shfl_xor_sync(0xffffffffu, s8v, 2);
            if ((lid & 3) == 0) {
                const int row0 = bm0 + warp_m * 64 + mt * 16 + rr;
                atomicAdd(&d2sq[row0], s0v);
                atomicAdd(&d2sq[row0 + 8], s8v);
            }
        }
    }
}

// ---------------- fp32 -> bf16 conversion (MLP=8, streaming) ----------------
__global__ void f32_to_bf16(const float4* __restrict__ in, uint2* __restrict__ out, int n4) {
    int base = blockIdx.x * (blockDim.x * 8) + threadIdx.x;
    float4 v[8];
#pragma unroll
    for (int k = 0; k < 8; k++) {
        int i = base + k * 256;
        if (i < n4) v[k] = __ldcs(in + i);
    }
#pragma unroll
    for (int k = 0; k < 8; k++) {
        int i = base + k * 256;
        if (i < n4) {
            __nv_bfloat162 a = __floats2bfloat162_rn(v[k].x, v[k].y);
            __nv_bfloat162 b = __floats2bfloat162_rn(v[k].z, v[k].w);
            __stcs(out + i, make_uint2(*(uint32_t*)&a, *(uint32_t*)&b));
        }
    }
}

// ---------------- reductions ----------------
__device__ __forceinline__ float block_reduce(float v) {
    __shared__ float sh[8];
    __syncthreads();
    int lane = threadIdx.x & 31;
    int w    = threadIdx.x >> 5;
#pragma unroll
    for (int o = 16; o > 0; o >>= 1) v += __shfl_down_sync(0xffffffffu, v, o);
    if (lane == 0) sh[w] = v;
    __syncthreads();
    if (w == 0) {
        v = (lane < 8) ? sh[lane] : 0.f;
#pragma unroll
        for (int o = 4; o > 0; o >>= 1) v += __shfl_down_sync(0xffffffffu, v, o);
    }
    return v;
}

__device__ __forceinline__ float d2_bf8(uint4 x, uint4 y) {
    float s = 0.f;
    const uint32_t* xp = (const uint32_t*)&x;
    const uint32_t* yp = (const uint32_t*)&y;
#pragma unroll
    for (int qq = 0; qq < 4; qq++) {
        float2 a = __bfloat1622float2(*(const __nv_bfloat162*)&xp[qq]);
        float2 b = __bfloat1622float2(*(const __nv_bfloat162*)&yp[qq]);
        float d0 = a.x - b.x, d1 = a.y - b.y;
        s += d0 * d0 + d1 * d1;
    }
    return s;
}

__global__ void zero_kernel() {
    int i = blockIdx.x * blockDim.x + threadIdx.x;
    if (i < NN) g_d2sq[i] = 0.f;
    if (i == 0) { g_acc[0] = 0.f; g_acc[1] = 0.f; g_acc[2] = 0.f; }
}

__global__ void edge_loss_kernel(const int* __restrict__ edges,
                                 const int* __restrict__ labels) {
    int e  = blockIdx.x;
    int ni = edges[2 * e + 0];
    int nj = edges[2 * e + 1];
    int lab = labels[e];

    if (lab != 0) {
        const uint4* hi1 = (const uint4*)(g_H1bf + (size_t)ni * HD);
        const uint4* hj1 = (const uint4*)(g_H1bf + (size_t)nj * HD);
        float s1 = 0.f;
        for (int c = threadIdx.x; c < HD / 8; c += blockDim.x)
            s1 += d2_bf8(hi1[c], hj1[c]);
        const uint4* hi2 = (const uint4*)(g_H2bf + (size_t)ni * NN);
        const uint4* hj2 = (const uint4*)(g_H2bf + (size_t)nj * NN);
        float s2 = 0.f;
        for (int c = threadIdx.x; c < NN / 8; c += blockDim.x)
            s2 += d2_bf8(hi2[c], hj2[c]);
        s1 = block_reduce(s1);
        s2 = block_reduce(s2);
        if (threadIdx.x == 0) atomicAdd(&g_acc[0], sqrtf(s1) + sqrtf(s2));
    }
    if (threadIdx.x == 0) {
        float factor = (lab != 0) ? 10.f : 1.f;
        atomicAdd(&g_acc[1], factor * (sqrtf(g_d2sq[ni]) + sqrtf(g_d2sq[nj])));
    }
}

// sum of row norms of W1, W2 plus ||b1||, ||b2|| (exact, fp32 inputs)
__global__ void reg_norm_kernel(const float* __restrict__ W1, const float* __restrict__ b1,
                                const float* __restrict__ W2, const float* __restrict__ b2) {
    int b = blockIdx.x;
    const float* p; int len;
    if (b < HD)            { p = W1 + (size_t)b * NN;        len = NN; }
    else if (b < HD + NN)  { p = W2 + (size_t)(b - HD) * HD; len = HD; }
    else if (b == HD + NN) { p = b1;                         len = HD; }
    else                   { p = b2;                         len = NN; }
    float s = 0.f;
    for (int c = threadIdx.x; c < len; c += blockDim.x) { float v = p[c]; s += v * v; }
    s = block_reduce(s);
    if (threadIdx.x == 0) atomicAdd(&g_acc[2], sqrtf(s));
}

__global__ void finalize_kernel(float* out) {
    out[0] = g_acc[0] + g_acc[1] + g_acc[2] * (float)EE;
}

// ---------------- launch ----------------
extern "C" void kernel_launch(void* const* d_in, const int* in_sizes, int n_in,
                              void* d_out, int out_size) {
    const float* A      = (const float*)d_in[0];
    const float* W1     = (const float*)d_in[1];
    const float* b1     = (const float*)d_in[2];
    const float* W2     = (const float*)d_in[3];
    const float* b2     = (const float*)d_in[4];
    const int*   edges  = (const int*)d_in[5];
    const int*   labels = (const int*)d_in[6];
    float* out = (float*)d_out;

    __nv_bfloat16 *Abf, *W1bf, *W2bf, *H1bf, *H2bf;
    float* d2sq;
    cudaGetSymbolAddress((void**)&Abf,  g_Abf);
    cudaGetSymbolAddress((void**)&W1bf, g_W1bf);
    cudaGetSymbolAddress((void**)&W2bf, g_W2bf);
    cudaGetSymbolAddress((void**)&H1bf, g_H1bf);
    cudaGetSymbolAddress((void**)&H2bf, g_H2bf);
    cudaGetSymbolAddress((void**)&d2sq, g_d2sq);

    cudaFuncSetAttribute(gemm_hmma_bias_sigmoid,
                         cudaFuncAttributeMaxDynamicSharedMemorySize, SMEM_BYTES);

    zero_kernel<<<NN / 256, 256>>>();

    // fp32 -> bf16 conversions (MLP=8)
    f32_to_bf16<<<NN * (NN / 4) / 2048, 256>>>((const float4*)A,  (uint2*)Abf,  NN * NN / 4);
    f32_to_bf16<<<HD * (NN / 4) / 2048, 256>>>((const float4*)W1, (uint2*)W1bf, HD * NN / 4);
    f32_to_bf16<<<NN * (HD / 4) / 2048, 256>>>((const float4*)W2, (uint2*)W2bf, NN * HD / 4);

    // H1 = sigmoid(A @ W1^T + b1): M=8192, Nc=1024, K=8192
    gemm_hmma_bias_sigmoid<<<dim3(HD / 128, NN / 128), 256, SMEM_BYTES>>>(
        Abf, W1bf, b1, H1bf, nullptr, nullptr, NN, HD);
    // H2 = sigmoid(H1 @ W2^T + b2): M=8192, Nc=8192, K=1024  (+ fused node residual)
    gemm_hmma_bias_sigmoid<<<dim3(NN / 128, NN / 128), 256, SMEM_BYTES>>>(
        H1bf, W2bf, b2, H2bf, A, d2sq, HD, NN);

    edge_loss_kernel<<<EE, 256>>>(edges, labels);
    reg_norm_kernel<<<HD + NN + 2, 256>>>(W1, b1, W2, b2);
    finalize_kernel<<<1, 1>>>(out);
}